// round 2
// baseline (speedup 1.0000x reference)
#include <cuda_runtime.h>
#include <math.h>

#define NL 4
#define H  1024
#define E  2048
#define G3 3072
#define OUTN 50257

// Scratch — persistent __device__ globals (no allocation allowed).
__device__ float g_x[E];            // current layer input (E = 2H)
__device__ float g_gi[2 * G3];      // W_ih @ x + b_ih
__device__ float g_gh[2 * G3];      // W_hh @ h + b_hh
__device__ unsigned int g_cnt = 0;  // block-completion counter (self-resetting)

__device__ __forceinline__ float sigmoidf(float x) {
    return 1.0f / (1.0f + expf(-x));
}

// ---------------------------------------------------------------------------
// Fused gates + (embed staging) + (tail combine).
//   grid = 768 blocks x 256 threads; warp-per-row, 8 rows/block.
//   Blocks 0..383 handle direction 0 rows, 384..767 direction 1.
//   Layer 0 stages x directly from the embedding table (no embed kernel).
//   The LAST block to finish (atomic counter) runs the GRU nonlinearity for
//   all 2048 (d,j) pairs, writes new hidden to d_out and g_x, resets counter.
// ---------------------------------------------------------------------------
__global__ void __launch_bounds__(256) gates_kernel(
    const float* __restrict__ wih, const float* __restrict__ whh,
    const float* __restrict__ bih, const float* __restrict__ bhh,
    const float* __restrict__ hidden, const float* __restrict__ table,
    const int* __restrict__ feat, float* __restrict__ out, int l) {

    __shared__ __align__(16) float sx[E];   // 8 KB
    __shared__ __align__(16) float sh[H];   // 4 KB
    __shared__ int s_islast;

    int tid  = threadIdx.x;
    int warp = tid >> 5, lane = tid & 31;

    int row0 = blockIdx.x * 8;              // first of 8 rows for this block
    int d = (row0 >= G3) ? 1 : 0;           // 8 consecutive rows share direction

    // Stage x (from embed table for layer 0, else from g_x) and h.
    if (l == 0) {
        size_t tb = (size_t)feat[0] * E;
        for (int i = tid; i < E; i += 256) sx[i] = table[tb + i];
    } else {
        for (int i = tid; i < E; i += 256) sx[i] = g_x[i];
    }
    {
        const float* hp = hidden + (size_t)(2 * l + d) * H;
        for (int i = tid; i < H; i += 256) sh[i] = hp[i];
    }
    __syncthreads();

    // Warp-per-row dot products, 16 + 8 independent float4 loads per lane.
    int row = row0 + warp;
    int j = row - d * G3;
    const float4* wi = (const float4*)(wih + ((size_t)(l * 2 + d) * G3 + j) * E);
    const float4* wh = (const float4*)(whh + ((size_t)(l * 2 + d) * G3 + j) * H);
    const float4* xv = (const float4*)sx;
    const float4* hv = (const float4*)sh;

    float si = 0.f, shh = 0.f;
    #pragma unroll
    for (int k = 0; k < 16; k++) {
        float4 w = wi[lane + k * 32];
        float4 x = xv[lane + k * 32];
        si += w.x * x.x + w.y * x.y + w.z * x.z + w.w * x.w;
    }
    #pragma unroll
    for (int k = 0; k < 8; k++) {
        float4 w = wh[lane + k * 32];
        float4 h = hv[lane + k * 32];
        shh += w.x * h.x + w.y * h.y + w.z * h.z + w.w * h.w;
    }
    #pragma unroll
    for (int o = 16; o; o >>= 1) {
        si  += __shfl_xor_sync(0xffffffffu, si, o);
        shh += __shfl_xor_sync(0xffffffffu, shh, o);
    }
    if (lane == 0) {
        size_t boff = (size_t)(l * 2 + d) * G3 + j;
        g_gi[row] = si  + bih[boff];
        g_gh[row] = shh + bhh[boff];
    }

    // ---- last-block-done: run the GRU combine for this layer ----
    __threadfence();
    __syncthreads();
    if (tid == 0) {
        unsigned int n = atomicAdd(&g_cnt, 1u);
        s_islast = (n == gridDim.x - 1u) ? 1 : 0;
    }
    __syncthreads();
    if (!s_islast) return;

    for (int idx = tid; idx < 2 * H; idx += 256) {
        int dd = (idx >= H) ? 1 : 0;
        int jj = idx - dd * H;
        int base = dd * G3;
        float ir  = g_gi[base + jj],         hr = g_gh[base + jj];
        float iz  = g_gi[base + H + jj],     hz = g_gh[base + H + jj];
        float in_ = g_gi[base + 2 * H + jj], hn = g_gh[base + 2 * H + jj];

        float r = sigmoidf(ir + hr);
        float z = sigmoidf(iz + hz);
        float n = tanhf(in_ + r * hn);
        float hold = hidden[(size_t)(2 * l + dd) * H + jj];
        float hnew = (1.0f - z) * n + z * hold;

        g_x[idx] = hnew;                                  // next layer input
        out[OUTN + (size_t)(2 * l + dd) * H + jj] = hnew; // new_hidden output
    }
    __syncthreads();
    if (tid == 0) g_cnt = 0;   // reset for next launch / graph replay
}

// ---------------------------------------------------------------------------
// FC: logits[r] = fc_w[r,:] . x + fc_b[r].  Warp-per-row, 8 rows/block,
// x staged once per block in shared; 16 independent float4 loads per lane.
// ---------------------------------------------------------------------------
__global__ void __launch_bounds__(256) fc_kernel(
    const float* __restrict__ fcw, const float* __restrict__ fcb,
    float* __restrict__ out) {

    __shared__ __align__(16) float sx[E];
    int tid = threadIdx.x;
    for (int i = tid; i < E; i += 256) sx[i] = g_x[i];
    __syncthreads();

    int warp = tid >> 5, lane = tid & 31;
    int r = blockIdx.x * 8 + warp;
    if (r >= OUTN) return;

    const float4* wr = (const float4*)(fcw + (size_t)r * E);
    const float4* xv = (const float4*)sx;

    float sum = 0.f;
    #pragma unroll
    for (int k = 0; k < 16; k++) {
        float4 w = wr[lane + k * 32];
        float4 x = xv[lane + k * 32];
        sum += w.x * x.x + w.y * x.y + w.z * x.z + w.w * x.w;
    }
    #pragma unroll
    for (int o = 16; o; o >>= 1) sum += __shfl_xor_sync(0xffffffffu, sum, o);

    if (lane == 0) out[r] = sum + fcb[r];
}

// ---------------------------------------------------------------------------
// Launch: 4 x fused-gates, then fc.  5 launches total, graph-capturable.
// Inputs (metadata order): features(i32), hidden, embed_table, w_ih, w_hh,
// b_ih, b_hh, fc_w, fc_b.  Output: logits[0,50257) then new_hidden.
// ---------------------------------------------------------------------------
extern "C" void kernel_launch(void* const* d_in, const int* in_sizes, int n_in,
                              void* d_out, int out_size) {
    const int*   feat   = (const int*)  d_in[0];
    const float* hidden = (const float*)d_in[1];
    const float* table  = (const float*)d_in[2];
    const float* wih    = (const float*)d_in[3];
    const float* whh    = (const float*)d_in[4];
    const float* bih    = (const float*)d_in[5];
    const float* bhh    = (const float*)d_in[6];
    const float* fcw    = (const float*)d_in[7];
    const float* fcb    = (const float*)d_in[8];
    float* out = (float*)d_out;

    for (int l = 0; l < NL; l++) {
        gates_kernel<<<768, 256>>>(wih, whh, bih, bhh, hidden, table, feat,
                                   out, l);
    }
    fc_kernel<<<(OUTN + 7) / 8, 256>>>(fcw, fcb, out);
}